// round 15
// baseline (speedup 1.0000x reference)
#include <cuda_runtime.h>

// Problem constants (fixed by setup_inputs: B=8,T=4096,D=1024,A=32,S=16,TTL=64)
#define NB_B 8
#define NB_T 4096
#define NB_D 1024
#define NB_A 32
#define SP   16
#define HH   256           // H = max(ttl*4, span*4)
#define WW   (HH - SP + 1) // 241
#define NPAIR (NB_B * NB_A)
#define CH   4             // column chunks (CTAs) per pair
#define CG   64            // float4 groups per chunk (256 floats)
#define NG   (NB_D / 4)    // 256 float4 groups per row
#define SRS  260           // srow padded stride

typedef unsigned long long u64;
#define ADDX2(r,a,b)   asm("add.rn.f32x2 %0, %1, %2;" : "=l"(r) : "l"(a), "l"(b))
#define FMAX2(r,a,b,c) asm("fma.rn.f32x2 %0, %1, %2, %3;" : "=l"(r) : "l"(a), "l"(b), "l"(c))
#define PACKX2(r,lo,hi) asm("mov.b64 %0, {%1, %2};" : "=l"(r) : "f"(lo), "f"(hi))
#define UNPKX2(lo,hi,v) asm("mov.b64 {%0, %1}, %2;" : "=f"(lo), "=f"(hi) : "l"(v))

// scratch
__device__ float g_rshift[NPAIR * HH * CH];  // per-(pair,row) chunk partial norms^2
__device__ float g_dot[NPAIR * CH];
__device__ float g_nf2[NPAIR * CH];
__device__ float g_nr2[NPAIR * CH];
__device__ unsigned int g_cnt[NPAIR];        // zero-init; reset by finalizer

__constant__ signed char c_alias[64] = {
  -1,-1,-1,-1,-1,-1,-1,-1,-1,-1,-1,
  11,-1,11,-1,-1,11,
  -1,-1,-1,-1,
  21,21,21,
  -1,-1,-1,-1,-1,-1,-1,
  31,31,31,
  -1,-1,-1,-1,-1,-1,-1,
  41,41,41,41,
  -1,-1,-1,-1,-1,-1,
  51,51,51,
  -1,-1,-1,-1,-1,-1,-1,-1,-1,-1
};

// ---- 1024 streaming CTAs (256-col slices) + 256 token/finalizer CTAs ----
__global__ void __launch_bounds__(256, 5) cm_stream(
    const float* __restrict__ hidden,
    const float* __restrict__ anchor,
    const int*   __restrict__ ids,
    const int*   __restrict__ aend,
    float*       __restrict__ out)
{
  const int blk  = blockIdx.x;
  const int tid  = threadIdx.x;
  const int lane = tid & 31;
  const int wp   = tid >> 5;

  if (blk < NPAIR * CH) {
    // ================= streaming CTA =================
    const int p     = blk >> 2;
    const int chunk = blk & 3;
    const int b     = p / NB_A;
    const int ae    = aend[p];
    const int start = ae + 1;

    // srow: per-lane row-norm partials [lane][row]; scs overlapped after barrier.
    __shared__ float srow[32 * SRS];     // 33.3 KB
    float4* scs = reinterpret_cast<float4*>(srow);
    __shared__ float  sfin[3 * 8];

    const u64* hbase = reinterpret_cast<const u64*>(hidden)
        + (((size_t)b * NB_T + start) * NG + chunk * CG) * 2;
    const float4* __restrict__ af =
        reinterpret_cast<const float4*>(anchor) + (size_t)p * NG + chunk * CG;

    const float4 a0 = af[lane];
    const float4 a1 = af[lane + 32];
    u64 na0x, na0z, na1x, na1z, zero64;
    PACKX2(na0x, -a0.x, -a0.y); PACKX2(na0z, -a0.z, -a0.w);
    PACKX2(na1x, -a1.x, -a1.y); PACKX2(na1z, -a1.z, -a1.w);
    PACKX2(zero64, 0.f, 0.f);
    u64 cs0x = zero64, cs0z = zero64, cs1x = zero64, cs1z = zero64;

    const int row0 = wp * 32;            // warp owns 32 rows
    float* __restrict__ myrow = srow + lane * SRS;
    // ulonglong2 view: row stride NG*2 u64, group g at offset g*2
    const int L2 = lane * 2;

#pragma unroll 1
    for (int it = 0; it < 8; it++) {
      const int r = row0 + it * 4;
      const u64* rp = hbase + (size_t)r * (NG * 2);
      // 8 independent LDG.128 front-batched -> MLP 8
      u64 xa[4], xb[4], ya[4], yb[4];
#pragma unroll
      for (int j = 0; j < 4; j++) {
        const u64* q = rp + (size_t)j * (NG * 2);
        xa[j] = q[L2];        xb[j] = q[L2 + 1];
        ya[j] = q[L2 + 64];   yb[j] = q[L2 + 65];
      }
      float v[4];
#pragma unroll
      for (int j = 0; j < 4; j++) {
        ADDX2(cs0x, cs0x, xa[j]); ADDX2(cs0z, cs0z, xb[j]);
        ADDX2(cs1x, cs1x, ya[j]); ADDX2(cs1z, cs1z, yb[j]);
        u64 d0, d1, d2, d3, vp;
        ADDX2(d0, xa[j], na0x); ADDX2(d1, xb[j], na0z);
        ADDX2(d2, ya[j], na1x); ADDX2(d3, yb[j], na1z);
        FMAX2(vp, d0, d0, zero64);
        FMAX2(vp, d1, d1, vp);
        FMAX2(vp, d2, d2, vp);
        FMAX2(vp, d3, d3, vp);
        float lo, hi; UNPKX2(lo, hi, vp);
        v[j] = lo + hi;
      }
      // one STS.128: (lane*SRS + r)*4 bytes, SRS*4=1040 ≡ 0 (mod 16), r%4==0
      *reinterpret_cast<float4*>(myrow + r) = make_float4(v[0], v[1], v[2], v[3]);
    }
    __syncthreads();

    // row-sum transpose: thread t reduces row t's 32 lane-partials (conflict-free)
    float rowsum = 0.f;
#pragma unroll
    for (int l = 0; l < 32; l++) rowsum += srow[l * SRS + tid];
    g_rshift[((size_t)p * HH + tid) * CH + chunk] = rowsum;

    __syncthreads();   // srow reads complete before scs (aliased) is written

    // unpack packed column sums
    float4 cs0, cs1;
    UNPKX2(cs0.x, cs0.y, cs0x); UNPKX2(cs0.z, cs0.w, cs0z);
    UNPKX2(cs1.x, cs1.y, cs1x); UNPKX2(cs1.z, cs1.w, cs1z);

    // combine warps' column sums -> chunk scalars
    scs[wp * 64 + lane]      = cs0;
    scs[wp * 64 + lane + 32] = cs1;
    __syncthreads();

    if (tid < 64) {
      float4 t = scs[tid];
#pragma unroll
      for (int w = 1; w < 8; w++) {
        float4 u = scs[w * 64 + tid];
        t.x += u.x; t.y += u.y; t.z += u.z; t.w += u.w;
      }
      float4 a = af[tid];
      float dot = a.x*t.x + a.y*t.y + a.z*t.z + a.w*t.w;
      float nf2 = t.x*t.x + t.y*t.y + t.z*t.z + t.w*t.w;
      float nr2 = a.x*a.x + a.y*a.y + a.z*a.z + a.w*a.w;
#pragma unroll
      for (int o = 16; o; o >>= 1) {
        dot += __shfl_xor_sync(0xffffffffu, dot, o);
        nf2 += __shfl_xor_sync(0xffffffffu, nf2, o);
        nr2 += __shfl_xor_sync(0xffffffffu, nr2, o);
      }
      if (lane == 0) {
        sfin[wp * 3 + 0] = dot; sfin[wp * 3 + 1] = nf2; sfin[wp * 3 + 2] = nr2;
      }
    }
    __syncthreads();
    if (tid == 0) {
      g_dot[blk] = sfin[0] + sfin[3];
      g_nf2[blk] = sfin[1] + sfin[4];
      g_nr2[blk] = sfin[2] + sfin[5];
      // release-publish this chunk (no MEMBAR/IVALL; ordering at L2)
      asm volatile("red.release.gpu.global.add.u32 [%0], 1;"
                   :: "l"(&g_cnt[p]) : "memory");
    }
    return;
  }

  // ================= token + finalizer CTA (one per pair) =================
  const int p = blk - NPAIR * CH;
  const int b = p / NB_A;
  const int ae    = aend[p];
  const int start = ae + 1;

  __shared__ float sred[56];
  __shared__ int   ftok[HH];
  __shared__ int   sp_[SP];
  __shared__ signed char s_alias[64];
  __shared__ int   s_root, s_has, s_atok;
  __shared__ float s_invden;
  __shared__ unsigned long long s_spanmask, s_cmask;

  if (tid < 64) s_alias[tid] = c_alias[tid];
  ftok[tid] = ids[b * NB_T + start + tid];
  if (tid < SP) sp_[tid] = ids[b * NB_T + ae - (SP - 1) + tid];
  if (tid == 0) s_atok = ids[b * NB_T + ae];
  __syncthreads();

  if (tid == 0) {
    int root = -1;
    for (int s = 0; s < SP; s++) {
      int al = s_alias[sp_[s]];
      if (al >= 0) { root = al; break; }
    }
    if (root < 0) {
      int counts[SP]; int maxc = 0;
      for (int s = 0; s < SP; s++) {
        int c2 = 0;
        for (int s2 = 0; s2 < SP; s2++) c2 += (sp_[s2] == sp_[s]);
        counts[s] = c2; if (c2 > maxc) maxc = c2;
      }
      int mode = 64;
      for (int s = 0; s < SP; s++)
        if (counts[s] == maxc && sp_[s] < mode) mode = sp_[s];
      root = mode;
    }
    unsigned long long smask = 0ull; int den = 0;
    for (int s = 0; s < SP; s++) {
      bool first = true;
      for (int s2 = 0; s2 < s; s2++)
        if (sp_[s2] == sp_[s]) { first = false; break; }
      if (first) { den++; smask |= (1ull << sp_[s]); }
    }
    s_root = root;
    s_spanmask = smask;
    s_invden = 1.f / (float)den;
    s_has = (root == 11 || root == 21 || root == 31 || root == 41 || root == 51) ? 1 : 0;
    unsigned long long cm = 0ull;
    switch (root) {
      case 11: cm = (1ull<<11)|(1ull<<13)|(1ull<<16); break;
      case 21: cm = (1ull<<14)|(1ull<<15)|(1ull<<21)|(1ull<<22)|(1ull<<23); break;
      case 31: cm = (1ull<<15)|(1ull<<31)|(1ull<<32)|(1ull<<33); break;
      case 41: cm = (1ull<<41)|(1ull<<42)|(1ull<<43)|(1ull<<44); break;
      case 51: cm = (1ull<<15)|(1ull<<51)|(1ull<<52)|(1ull<<53); break;
      default: break;
    }
    s_cmask = cm;
  }
  __syncthreads();

  int myeq = (ftok[tid] == s_atok) ? 1 : 0;

  float sims = -1e30f, rootp = 0.f, regime = 0.f, ssum = 0.f;
  int c06 = 0;
  if (tid < WW) {
    const int root = s_root;
    const unsigned long long cmask = s_cmask;
    float exact = 0.f, positional = 0.f;
    unsigned long long wmask = 0ull;
    int c_rp = 0, c_al = 0, c_hd = 0;
#pragma unroll
    for (int s = 0; s < SP; s++) {
      int t = ftok[tid + s];
      wmask |= (1ull << t);
      if (t == sp_[s]) { exact += 1.f; positional += (1.0f - 0.04f * (float)s); }
      c_rp += (t == root);
      c_al += ((int)s_alias[t] == root);
      c_hd += (int)((cmask >> t) & 1ull);
    }
    exact *= (1.f / 16.f);
    positional *= (1.f / 11.2f);
    float overlap = (float)__popcll(wmask & s_spanmask) * s_invden;
    rootp = (float)c_rp * (1.f / 16.f);
    float aliasc = (float)c_al * (1.f / 16.f);
    float hard   = (float)c_hd * (1.f / 16.f);
    regime = s_has ? (0.55f * hard  + 0.2f * overlap + 0.15f * aliasc + 0.1f  * rootp)
                   : (0.45f * exact + 0.3f * overlap + 0.1f  * aliasc + 0.15f * rootp);
    float sv = 0.25f * exact + 0.15f * overlap + 0.35f * positional + 0.25f * regime;
    sims = sv; ssum = sv;
    c06 = (sv >= 0.6f) ? 1 : 0;
  }

  float msims = sims, srp = rootp, srg = regime, sss = ssum;
  int ceq = myeq, c6 = c06;
#pragma unroll
  for (int o = 16; o; o >>= 1) {
    msims = fmaxf(msims, __shfl_xor_sync(0xffffffffu, msims, o));
    srp += __shfl_xor_sync(0xffffffffu, srp, o);
    srg += __shfl_xor_sync(0xffffffffu, srg, o);
    sss += __shfl_xor_sync(0xffffffffu, sss, o);
    ceq += __shfl_xor_sync(0xffffffffu, ceq, o);
    c6  += __shfl_xor_sync(0xffffffffu, c6, o);
  }
  if (lane == 0) {
    sred[wp]      = msims;
    sred[8 + wp]  = srp;
    sred[16 + wp] = srg;
    sred[24 + wp] = sss;
    sred[32 + wp] = (float)ceq;
    sred[40 + wp] = (float)c6;
  }
  __syncthreads();

  // token scalars (held in tid0 registers across the wait)
  float best = -1e30f, trp = 0.f, trg = 0.f, tss = 0.f, teq = 0.f, t6 = 0.f;
  if (tid == 0) {
    for (int k = 0; k < 8; k++) {
      best = fmaxf(best, sred[k]);
      trp += sred[8 + k]; trg += sred[16 + k]; tss += sred[24 + k];
      teq += sred[32 + k]; t6 += sred[40 + k];
    }
    // acquire-spin until this pair's 4 streaming chunks have published
    unsigned int v;
    do {
      asm volatile("ld.acquire.gpu.global.u32 %0, [%1];"
                   : "=r"(v) : "l"(&g_cnt[p]) : "memory");
      if (v == CH) break;
      __nanosleep(64);
    } while (1);
    g_cnt[p] = 0;   // reset for next graph replay (kernel boundary orders it)
  }
  __syncthreads();

  // row-norm finalization: thread tid owns row tid
  float4 rp4 = reinterpret_cast<const float4*>(g_rshift)[p * HH + tid];
  float rn = sqrtf(rp4.x + rp4.y + rp4.z + rp4.w);
#pragma unroll
  for (int o = 16; o; o >>= 1) rn += __shfl_xor_sync(0xffffffffu, rn, o);
  if (lane == 0) sred[48 + wp] = rn;
  __syncthreads();

  if (tid == 0) {
    float sh = 0.f;
#pragma unroll
    for (int k = 0; k < 8; k++) sh += sred[48 + k];
    float shift = sh * (1.f / HH);

    float dot = 0.f, nf2 = 0.f, nr2 = 0.f;
#pragma unroll
    for (int c = 0; c < CH; c++) {
      dot += g_dot[p * CH + c];
      nf2 += g_nf2[p * CH + c];
      nr2 += g_nr2[p * CH + c];
    }
    const float eps = 1e-8f;
    float nr = fmaxf(sqrtf(nr2), eps);
    float nf = fmaxf(sqrtf(nf2) * (1.f / HH), eps);
    float sim = (dot * (1.f / HH)) / (nr * nf);
    float hidden_c = fmaxf(0.f, (1.f - sim) * 0.5f);
    float token_c = 1.f - teq * (1.f / HH);
    const float invW = 1.f / (float)WW;
    float mrp = trp * invW, mrc = trg * invW;
    float dmass = t6 * invW;
    float dcoh = 0.6f * (tss * invW) + 0.25f * mrp + 0.15f * mrc;
    float pattern_c = 1.f - (0.6f * best + 0.2f * mrp + 0.2f * mrc);
    float contr = fminf(1.f, fmaxf(0.f, 0.2f * hidden_c + 0.2f * token_c + 0.6f * pattern_c));

    out[0 * NPAIR + p] = contr;
    out[1 * NPAIR + p] = shift;
    out[2 * NPAIR + p] = sim;
    out[3 * NPAIR + p] = hidden_c;
    out[4 * NPAIR + p] = token_c;
    out[5 * NPAIR + p] = pattern_c;
    out[6 * NPAIR + p] = dmass;
    out[7 * NPAIR + p] = dcoh;
  }
}

extern "C" void kernel_launch(void* const* d_in, const int* in_sizes, int n_in,
                              void* d_out, int out_size) {
  (void)in_sizes; (void)n_in; (void)out_size;
  const float* hidden = (const float*)d_in[0];
  const float* anchor = (const float*)d_in[1];
  const int*   ids    = (const int*)d_in[2];
  const int*   aendp  = (const int*)d_in[3];
  cm_stream<<<NPAIR * CH + NPAIR, 256>>>(hidden, anchor, ids, aendp, (float*)d_out);
}

// round 16
// speedup vs baseline: 1.1989x; 1.1989x over previous
#include <cuda_runtime.h>

// Problem constants (fixed by setup_inputs: B=8,T=4096,D=1024,A=32,S=16,TTL=64)
#define NB_B 8
#define NB_T 4096
#define NB_D 1024
#define NB_A 32
#define SP   16
#define HH   256           // H = max(ttl*4, span*4)
#define WW   (HH - SP + 1) // 241
#define NPAIR (NB_B * NB_A)
#define CH   4             // column chunks (CTAs) per pair
#define CG   64            // float4 groups per chunk (256 floats)
#define NG   (NB_D / 4)    // 256 float4 groups per row
#define SRS  260           // srow padded stride

typedef unsigned long long u64;
#define ADDX2(r,a,b)   asm("add.rn.f32x2 %0, %1, %2;" : "=l"(r) : "l"(a), "l"(b))
#define FMAX2(r,a,b,c) asm("fma.rn.f32x2 %0, %1, %2, %3;" : "=l"(r) : "l"(a), "l"(b), "l"(c))
#define PACKX2(r,lo,hi) asm("mov.b64 %0, {%1, %2};" : "=l"(r) : "f"(lo), "f"(hi))
#define UNPKX2(lo,hi,v) asm("mov.b64 {%0, %1}, %2;" : "=f"(lo), "=f"(hi) : "l"(v))

// scratch
__device__ float g_rshift[NPAIR * HH * CH];  // per-(pair,row) chunk partial norms^2
__device__ float g_dot[NPAIR * CH];
__device__ float g_nf2[NPAIR * CH];
__device__ float g_nr2[NPAIR * CH];
__device__ unsigned int g_cnt[NPAIR];        // zero-init; reset by finalizer

__constant__ signed char c_alias[64] = {
  -1,-1,-1,-1,-1,-1,-1,-1,-1,-1,-1,
  11,-1,11,-1,-1,11,
  -1,-1,-1,-1,
  21,21,21,
  -1,-1,-1,-1,-1,-1,-1,
  31,31,31,
  -1,-1,-1,-1,-1,-1,-1,
  41,41,41,41,
  -1,-1,-1,-1,-1,-1,
  51,51,51,
  -1,-1,-1,-1,-1,-1,-1,-1,-1,-1
};

// ---- 1024 streaming CTAs (256-col slices) + 256 token/finalizer CTAs ----
__global__ void __launch_bounds__(256, 4) cm_stream(
    const float* __restrict__ hidden,
    const float* __restrict__ anchor,
    const int*   __restrict__ ids,
    const int*   __restrict__ aend,
    float*       __restrict__ out)
{
  const int blk  = blockIdx.x;
  const int tid  = threadIdx.x;
  const int lane = tid & 31;
  const int wp   = tid >> 5;

  if (blk < NPAIR * CH) {
    // ================= streaming CTA =================
    const int p     = blk >> 2;
    const int chunk = blk & 3;
    const int b     = p / NB_A;
    const int ae    = aend[p];
    const int start = ae + 1;

    // srow: per-lane row-norm partials [lane][row]; scs overlapped after barrier.
    __shared__ float srow[32 * SRS];     // 33.3 KB
    float4* scs = reinterpret_cast<float4*>(srow);
    __shared__ float  sfin[3 * 8];

    const float4* __restrict__ hb =
        reinterpret_cast<const float4*>(hidden)
        + ((size_t)b * NB_T + start) * NG + chunk * CG;
    const float4* __restrict__ af =
        reinterpret_cast<const float4*>(anchor) + (size_t)p * NG + chunk * CG;

    const float4 a0 = af[lane];
    const float4 a1 = af[lane + 32];
    u64 na0x, na0z, na1x, na1z, zero64;
    PACKX2(na0x, -a0.x, -a0.y); PACKX2(na0z, -a0.z, -a0.w);
    PACKX2(na1x, -a1.x, -a1.y); PACKX2(na1z, -a1.z, -a1.w);
    PACKX2(zero64, 0.f, 0.f);
    u64 cs0x = zero64, cs0z = zero64, cs1x = zero64, cs1z = zero64;

    const int row0 = wp * 32;            // warp owns 32 rows
    float* __restrict__ myrow = srow + lane * SRS;

#pragma unroll 1
    for (int it = 0; it < 8; it++) {
      const int r = row0 + it * 4;
      const float4* __restrict__ rp = hb + (size_t)r * NG;
      // 8 independent LDG.128 front-batched -> MLP 8 (identical to R13)
      float4 x[4], y[4];
#pragma unroll
      for (int j = 0; j < 4; j++) {
        x[j] = rp[(size_t)j * NG + lane];
        y[j] = rp[(size_t)j * NG + lane + 32];
      }
      float v[4];
#pragma unroll
      for (int j = 0; j < 4; j++) {
        // repack float4 register quads into f32x2 operands (mov.b64 — cheap)
        u64 x01, x23, y01, y23;
        PACKX2(x01, x[j].x, x[j].y); PACKX2(x23, x[j].z, x[j].w);
        PACKX2(y01, y[j].x, y[j].y); PACKX2(y23, y[j].z, y[j].w);
        ADDX2(cs0x, cs0x, x01); ADDX2(cs0z, cs0z, x23);
        ADDX2(cs1x, cs1x, y01); ADDX2(cs1z, cs1z, y23);
        u64 d0, d1, d2, d3, vp;
        ADDX2(d0, x01, na0x); ADDX2(d1, x23, na0z);
        ADDX2(d2, y01, na1x); ADDX2(d3, y23, na1z);
        FMAX2(vp, d0, d0, zero64);
        FMAX2(vp, d1, d1, vp);
        FMAX2(vp, d2, d2, vp);
        FMAX2(vp, d3, d3, vp);
        float lo, hi; UNPKX2(lo, hi, vp);
        v[j] = lo + hi;
      }
      // one STS.128: (lane*SRS + r)*4 bytes, SRS*4=1040 ≡ 0 (mod 16), r%4==0
      *reinterpret_cast<float4*>(myrow + r) = make_float4(v[0], v[1], v[2], v[3]);
    }
    __syncthreads();

    // row-sum transpose: thread t reduces row t's 32 lane-partials (conflict-free)
    float rowsum = 0.f;
#pragma unroll
    for (int l = 0; l < 32; l++) rowsum += srow[l * SRS + tid];
    g_rshift[((size_t)p * HH + tid) * CH + chunk] = rowsum;

    __syncthreads();   // srow reads complete before scs (aliased) is written

    // unpack packed column sums
    float4 cs0, cs1;
    UNPKX2(cs0.x, cs0.y, cs0x); UNPKX2(cs0.z, cs0.w, cs0z);
    UNPKX2(cs1.x, cs1.y, cs1x); UNPKX2(cs1.z, cs1.w, cs1z);

    // combine warps' column sums -> chunk scalars
    scs[wp * 64 + lane]      = cs0;
    scs[wp * 64 + lane + 32] = cs1;
    __syncthreads();

    if (tid < 64) {
      float4 t = scs[tid];
#pragma unroll
      for (int w = 1; w < 8; w++) {
        float4 u = scs[w * 64 + tid];
        t.x += u.x; t.y += u.y; t.z += u.z; t.w += u.w;
      }
      float4 a = af[tid];
      float dot = a.x*t.x + a.y*t.y + a.z*t.z + a.w*t.w;
      float nf2 = t.x*t.x + t.y*t.y + t.z*t.z + t.w*t.w;
      float nr2 = a.x*a.x + a.y*a.y + a.z*a.z + a.w*a.w;
#pragma unroll
      for (int o = 16; o; o >>= 1) {
        dot += __shfl_xor_sync(0xffffffffu, dot, o);
        nf2 += __shfl_xor_sync(0xffffffffu, nf2, o);
        nr2 += __shfl_xor_sync(0xffffffffu, nr2, o);
      }
      if (lane == 0) {
        sfin[wp * 3 + 0] = dot; sfin[wp * 3 + 1] = nf2; sfin[wp * 3 + 2] = nr2;
      }
    }
    __syncthreads();
    if (tid == 0) {
      g_dot[blk] = sfin[0] + sfin[3];
      g_nf2[blk] = sfin[1] + sfin[4];
      g_nr2[blk] = sfin[2] + sfin[5];
      // release-publish this chunk (no MEMBAR/IVALL; ordering at L2)
      asm volatile("red.release.gpu.global.add.u32 [%0], 1;"
                   :: "l"(&g_cnt[p]) : "memory");
    }
    return;
  }

  // ================= token + finalizer CTA (one per pair) =================
  const int p = blk - NPAIR * CH;
  const int b = p / NB_A;
  const int ae    = aend[p];
  const int start = ae + 1;

  __shared__ float sred[56];
  __shared__ int   ftok[HH];
  __shared__ int   sp_[SP];
  __shared__ signed char s_alias[64];
  __shared__ int   s_root, s_has, s_atok;
  __shared__ float s_invden;
  __shared__ unsigned long long s_spanmask, s_cmask;

  if (tid < 64) s_alias[tid] = c_alias[tid];
  ftok[tid] = ids[b * NB_T + start + tid];
  if (tid < SP) sp_[tid] = ids[b * NB_T + ae - (SP - 1) + tid];
  if (tid == 0) s_atok = ids[b * NB_T + ae];
  __syncthreads();

  if (tid == 0) {
    int root = -1;
    for (int s = 0; s < SP; s++) {
      int al = s_alias[sp_[s]];
      if (al >= 0) { root = al; break; }
    }
    if (root < 0) {
      int counts[SP]; int maxc = 0;
      for (int s = 0; s < SP; s++) {
        int c2 = 0;
        for (int s2 = 0; s2 < SP; s2++) c2 += (sp_[s2] == sp_[s]);
        counts[s] = c2; if (c2 > maxc) maxc = c2;
      }
      int mode = 64;
      for (int s = 0; s < SP; s++)
        if (counts[s] == maxc && sp_[s] < mode) mode = sp_[s];
      root = mode;
    }
    unsigned long long smask = 0ull; int den = 0;
    for (int s = 0; s < SP; s++) {
      bool first = true;
      for (int s2 = 0; s2 < s; s2++)
        if (sp_[s2] == sp_[s]) { first = false; break; }
      if (first) { den++; smask |= (1ull << sp_[s]); }
    }
    s_root = root;
    s_spanmask = smask;
    s_invden = 1.f / (float)den;
    s_has = (root == 11 || root == 21 || root == 31 || root == 41 || root == 51) ? 1 : 0;
    unsigned long long cm = 0ull;
    switch (root) {
      case 11: cm = (1ull<<11)|(1ull<<13)|(1ull<<16); break;
      case 21: cm = (1ull<<14)|(1ull<<15)|(1ull<<21)|(1ull<<22)|(1ull<<23); break;
      case 31: cm = (1ull<<15)|(1ull<<31)|(1ull<<32)|(1ull<<33); break;
      case 41: cm = (1ull<<41)|(1ull<<42)|(1ull<<43)|(1ull<<44); break;
      case 51: cm = (1ull<<15)|(1ull<<51)|(1ull<<52)|(1ull<<53); break;
      default: break;
    }
    s_cmask = cm;
  }
  __syncthreads();

  int myeq = (ftok[tid] == s_atok) ? 1 : 0;

  float sims = -1e30f, rootp = 0.f, regime = 0.f, ssum = 0.f;
  int c06 = 0;
  if (tid < WW) {
    const int root = s_root;
    const unsigned long long cmask = s_cmask;
    float exact = 0.f, positional = 0.f;
    unsigned long long wmask = 0ull;
    int c_rp = 0, c_al = 0, c_hd = 0;
#pragma unroll
    for (int s = 0; s < SP; s++) {
      int t = ftok[tid + s];
      wmask |= (1ull << t);
      if (t == sp_[s]) { exact += 1.f; positional += (1.0f - 0.04f * (float)s); }
      c_rp += (t == root);
      c_al += ((int)s_alias[t] == root);
      c_hd += (int)((cmask >> t) & 1ull);
    }
    exact *= (1.f / 16.f);
    positional *= (1.f / 11.2f);
    float overlap = (float)__popcll(wmask & s_spanmask) * s_invden;
    rootp = (float)c_rp * (1.f / 16.f);
    float aliasc = (float)c_al * (1.f / 16.f);
    float hard   = (float)c_hd * (1.f / 16.f);
    regime = s_has ? (0.55f * hard  + 0.2f * overlap + 0.15f * aliasc + 0.1f  * rootp)
                   : (0.45f * exact + 0.3f * overlap + 0.1f  * aliasc + 0.15f * rootp);
    float sv = 0.25f * exact + 0.15f * overlap + 0.35f * positional + 0.25f * regime;
    sims = sv; ssum = sv;
    c06 = (sv >= 0.6f) ? 1 : 0;
  }

  float msims = sims, srp = rootp, srg = regime, sss = ssum;
  int ceq = myeq, c6 = c06;
#pragma unroll
  for (int o = 16; o; o >>= 1) {
    msims = fmaxf(msims, __shfl_xor_sync(0xffffffffu, msims, o));
    srp += __shfl_xor_sync(0xffffffffu, srp, o);
    srg += __shfl_xor_sync(0xffffffffu, srg, o);
    sss += __shfl_xor_sync(0xffffffffu, sss, o);
    ceq += __shfl_xor_sync(0xffffffffu, ceq, o);
    c6  += __shfl_xor_sync(0xffffffffu, c6, o);
  }
  if (lane == 0) {
    sred[wp]      = msims;
    sred[8 + wp]  = srp;
    sred[16 + wp] = srg;
    sred[24 + wp] = sss;
    sred[32 + wp] = (float)ceq;
    sred[40 + wp] = (float)c6;
  }
  __syncthreads();

  // token scalars (held in tid0 registers across the wait)
  float best = -1e30f, trp = 0.f, trg = 0.f, tss = 0.f, teq = 0.f, t6 = 0.f;
  if (tid == 0) {
    for (int k = 0; k < 8; k++) {
      best = fmaxf(best, sred[k]);
      trp += sred[8 + k]; trg += sred[16 + k]; tss += sred[24 + k];
      teq += sred[32 + k]; t6 += sred[40 + k];
    }
    // acquire-spin until this pair's 4 streaming chunks have published
    unsigned int v;
    do {
      asm volatile("ld.acquire.gpu.global.u32 %0, [%1];"
                   : "=r"(v) : "l"(&g_cnt[p]) : "memory");
      if (v == CH) break;
      __nanosleep(64);
    } while (1);
    g_cnt[p] = 0;   // reset for next graph replay (kernel boundary orders it)
  }
  __syncthreads();

  // row-norm finalization: thread tid owns row tid
  float4 rp4 = reinterpret_cast<const float4*>(g_rshift)[p * HH + tid];
  float rn = sqrtf(rp4.x + rp4.y + rp4.z + rp4.w);
#pragma unroll
  for (int o = 16; o; o >>= 1) rn += __shfl_xor_sync(0xffffffffu, rn, o);
  if (lane == 0) sred[48 + wp] = rn;
  __syncthreads();

  if (tid == 0) {
    float sh = 0.f;
#pragma unroll
    for (int k = 0; k < 8; k++) sh += sred[48 + k];
    float shift = sh * (1.f / HH);

    float dot = 0.f, nf2 = 0.f, nr2 = 0.f;
#pragma unroll
    for (int c = 0; c < CH; c++) {
      dot += g_dot[p * CH + c];
      nf2 += g_nf2[p * CH + c];
      nr2 += g_nr2[p * CH + c];
    }
    const float eps = 1e-8f;
    float nr = fmaxf(sqrtf(nr2), eps);
    float nf = fmaxf(sqrtf(nf2) * (1.f / HH), eps);
    float sim = (dot * (1.f / HH)) / (nr * nf);
    float hidden_c = fmaxf(0.f, (1.f - sim) * 0.5f);
    float token_c = 1.f - teq * (1.f / HH);
    const float invW = 1.f / (float)WW;
    float mrp = trp * invW, mrc = trg * invW;
    float dmass = t6 * invW;
    float dcoh = 0.6f * (tss * invW) + 0.25f * mrp + 0.15f * mrc;
    float pattern_c = 1.f - (0.6f * best + 0.2f * mrp + 0.2f * mrc);
    float contr = fminf(1.f, fmaxf(0.f, 0.2f * hidden_c + 0.2f * token_c + 0.6f * pattern_c));

    out[0 * NPAIR + p] = contr;
    out[1 * NPAIR + p] = shift;
    out[2 * NPAIR + p] = sim;
    out[3 * NPAIR + p] = hidden_c;
    out[4 * NPAIR + p] = token_c;
    out[5 * NPAIR + p] = pattern_c;
    out[6 * NPAIR + p] = dmass;
    out[7 * NPAIR + p] = dcoh;
  }
}

extern "C" void kernel_launch(void* const* d_in, const int* in_sizes, int n_in,
                              void* d_out, int out_size) {
  (void)in_sizes; (void)n_in; (void)out_size;
  const float* hidden = (const float*)d_in[0];
  const float* anchor = (const float*)d_in[1];
  const int*   ids    = (const int*)d_in[2];
  const int*   aendp  = (const int*)d_in[3];
  cm_stream<<<NPAIR * CH + NPAIR, 256>>>(hidden, anchor, ids, aendp, (float*)d_out);
}